// round 8
// baseline (speedup 1.0000x reference)
#include <cuda_runtime.h>

#define NB 8
#define NG 64
#define HH 256
#define HW 65536
#define NO 256
#define EPSBN 1e-5f

// per-(b,g): {coef0, coef1, coef2, bias1} with bn1 scale folded in
__device__ float g_coef[NB * NG * 4];

__device__ __forceinline__ unsigned long long pack2(float lo, float hi) {
    unsigned long long r;
    asm("mov.b64 %0, {%1, %2};" : "=l"(r) : "f"(lo), "f"(hi));
    return r;
}
__device__ __forceinline__ unsigned long long ffma2(unsigned long long a,
                                                    unsigned long long b,
                                                    unsigned long long c) {
    unsigned long long d;
    asm("fma.rn.f32x2 %0, %1, %2, %3;" : "=l"(d) : "l"(a), "l"(b), "l"(c));
    return d;
}
__device__ __forceinline__ float f2sum(unsigned long long a) {
    float lo = __uint_as_float((unsigned)(a & 0xffffffffull));
    float hi = __uint_as_float((unsigned)(a >> 32));
    return lo + hi;
}

// ---------------------------------------------------------------------------
// Kernel 1: per (b,g) attention weights (unchanged).
// ---------------------------------------------------------------------------
__global__ __launch_bounds__(256) void attn_kernel(
    const float* __restrict__ x,
    const float* __restrict__ attnconv_w,
    const float* __restrict__ bn1_gamma,
    const float* __restrict__ bn1_beta,
    const float* __restrict__ bn1_mean,
    const float* __restrict__ bn1_var) {
    int bg = blockIdx.x;            // b*64 + g
    int g  = bg & 63;
    const float* xb = x + (size_t)bg * 3 * HW;   // (b*192 + g*3) * HW

    float qk[9];
#pragma unroll
    for (int i = 0; i < 9; i++) qk[i] = 0.f;

    for (int w = threadIdx.x; w < 4096; w += blockDim.x) {
        int wy = w >> 6, wx = w & 63;
        float mx[3], av[3];
#pragma unroll
        for (int j = 0; j < 3; j++) {
            const float4* row = (const float4*)(xb + (size_t)j * HW) + wy * 256 + wx;
            float4 r0 = row[0];
            float4 r1 = row[64];
            float4 r2 = row[128];
            float4 r3 = row[192];
            float s = (r0.x + r0.y + r0.z + r0.w) + (r1.x + r1.y + r1.z + r1.w)
                    + (r2.x + r2.y + r2.z + r2.w) + (r3.x + r3.y + r3.z + r3.w);
            float m = fmaxf(fmaxf(fmaxf(r0.x, r0.y), fmaxf(r0.z, r0.w)),
                     fmaxf(fmaxf(fmaxf(r1.x, r1.y), fmaxf(r1.z, r1.w)),
                     fmaxf(fmaxf(fmaxf(r2.x, r2.y), fmaxf(r2.z, r2.w)),
                           fmaxf(fmaxf(r3.x, r3.y), fmaxf(r3.z, r3.w)))));
            mx[j] = m;
            av[j] = s * (1.f / 16.f);
        }
#pragma unroll
        for (int i = 0; i < 3; i++)
#pragma unroll
            for (int j = 0; j < 3; j++)
                qk[i * 3 + j] += mx[i] * av[j];
    }

    __shared__ float red[8][9];
    int lane = threadIdx.x & 31, warp = threadIdx.x >> 5;
#pragma unroll
    for (int i = 0; i < 9; i++) {
        float v = qk[i];
#pragma unroll
        for (int o = 16; o > 0; o >>= 1) v += __shfl_down_sync(0xffffffffu, v, o);
        if (lane == 0) red[warp][i] = v;
    }
    __syncthreads();

    if (threadIdx.x == 0) {
        float q9[9];
#pragma unroll
        for (int i = 0; i < 9; i++) {
            float s = 0.f;
#pragma unroll
            for (int w8 = 0; w8 < 8; w8++) s += red[w8][i];
            q9[i] = s;
        }
        float w0 = attnconv_w[g * 3 + 0];
        float w1 = attnconv_w[g * 3 + 1];
        float w2 = attnconv_w[g * 3 + 2];
        float t[3];
#pragma unroll
        for (int j = 0; j < 3; j++)
            t[j] = (q9[j] * w0 + q9[3 + j] * w1 + q9[6 + j] * w2) * (4.0f / HH);
        float m = fmaxf(t[0], fmaxf(t[1], t[2]));
        float e0 = expf(t[0] - m), e1 = expf(t[1] - m), e2 = expf(t[2] - m);
        float inv = 1.f / (e0 + e1 + e2);
        float s1 = bn1_gamma[g] * rsqrtf(bn1_var[g] + EPSBN);
        float* cp = &g_coef[bg * 4];
        cp[0] = e0 * inv * s1;
        cp[1] = e1 * inv * s1;
        cp[2] = e2 * inv * s1;
        cp[3] = bn1_beta[g] - s1 * bn1_mean[g];
    }
}

// ---------------------------------------------------------------------------
// Kernel 2: fused V-build + 256x64 GEMM + BN2, k-PAIRED f32x2 operands.
//   Wsh2[k2][o]  (u64) = (W[o][2k2]  , W[o][2k2+1])   * bn2scale[o]
//   Vsh2[k2][px] (u64) = (V[2k2][px] , V[2k2+1][px])
//   acc[o][px] (f32x2) += Wsh2[k2][o] * Vsh2[k2][px]; result = lo+hi.
// No splat MOVs: both operands load directly from smem as u64 pairs.
// Tile: M=256, N=128 px, K=64 (32 k2).  512 threads, 8o x 8px per thread.
// ---------------------------------------------------------------------------
__global__ __launch_bounds__(512, 1) void fused_gemm_kernel(
    const float* __restrict__ x,
    const float* __restrict__ conv_w,
    const float* __restrict__ bn2_gamma,
    const float* __restrict__ bn2_beta,
    const float* __restrict__ bn2_mean,
    const float* __restrict__ bn2_var,
    float* __restrict__ out) {
    extern __shared__ float smem[];
    unsigned long long* Wsh2 = (unsigned long long*)smem;          // [32][256] u64 = 64KB
    unsigned long long* Vsh2 = Wsh2 + 32 * 256;                    // [32][128] u64 = 32KB
    float* bsh = (float*)(Vsh2 + 32 * 128);                        // [256] bn2 bias
    float* ssh = bsh + 256;                                        // [256] bn2 scale

    int b   = blockIdx.y;
    int n0  = blockIdx.x * 128;
    int tid = threadIdx.x;

    if (tid < 256) {
        float s2 = bn2_gamma[tid] * rsqrtf(bn2_var[tid] + EPSBN);
        ssh[tid] = s2;
        bsh[tid] = bn2_beta[tid] - s2 * bn2_mean[tid];
    }
    __syncthreads();

    // Stage W as k-pairs folded with bn2 scale. conv_w[o][2k2..2k2+1] -> u64.
    for (int i = tid; i < 32 * 256; i += 512) {
        int k2 = i >> 8, o = i & 255;
        float2 w = *(const float2*)(conv_w + o * 64 + 2 * k2);
        float s = ssh[o];
        Wsh2[k2 * 256 + o] = pack2(w.x * s, w.y * s);
    }

    // Build V as k-pairs: thread handles one k2 and 2 pixels -> one STS.128.
    for (int i = tid; i < 32 * 64; i += 512) {
        int k2 = i >> 6, t2 = i & 63;
        int px = t2 * 2;
        const float* cp0 = &g_coef[(b * 64 + 2 * k2) * 4];
        const float* cp1 = cp0 + 4;
        size_t base0 = ((size_t)(b * 192 + (2 * k2) * 3)) * HW + n0 + px;
        size_t base1 = base0 + 3 * HW;
        float2 a0 = *(const float2*)(x + base0);
        float2 a1 = *(const float2*)(x + base0 + HW);
        float2 a2 = *(const float2*)(x + base0 + 2 * HW);
        float2 b0 = *(const float2*)(x + base1);
        float2 b1 = *(const float2*)(x + base1 + HW);
        float2 b2 = *(const float2*)(x + base1 + 2 * HW);
        float vlo0 = fmaxf(fmaf(cp0[0], a0.x, fmaf(cp0[1], a1.x, fmaf(cp0[2], a2.x, cp0[3]))), 0.f);
        float vlo1 = fmaxf(fmaf(cp0[0], a0.y, fmaf(cp0[1], a1.y, fmaf(cp0[2], a2.y, cp0[3]))), 0.f);
        float vhi0 = fmaxf(fmaf(cp1[0], b0.x, fmaf(cp1[1], b1.x, fmaf(cp1[2], b2.x, cp1[3]))), 0.f);
        float vhi1 = fmaxf(fmaf(cp1[0], b0.y, fmaf(cp1[1], b1.y, fmaf(cp1[2], b2.y, cp1[3]))), 0.f);
        float4 pr;
        pr.x = vlo0; pr.y = vhi0;   // u64 for px
        pr.z = vlo1; pr.w = vhi1;   // u64 for px+1
        *(float4*)(Vsh2 + k2 * 128 + px) = pr;
    }
    __syncthreads();

    int tn = tid & 15;        // pixel group  (px = tn*4 + m*64)
    int to = tid >> 4;        // output group (o = to*8 + j)
    int o0 = to * 8;

    unsigned long long acc[8][8];
#pragma unroll
    for (int j = 0; j < 8; j++)
#pragma unroll
        for (int p = 0; p < 8; p++) acc[j][p] = 0ull;

#pragma unroll 4
    for (int k2 = 0; k2 < 32; k2++) {
        const unsigned long long* wr = Wsh2 + k2 * 256 + o0;
        unsigned long long wp[8];
#pragma unroll
        for (int q = 0; q < 4; q++) {
            ulonglong2 wpair = *(const ulonglong2*)(wr + 2 * q);
            wp[2 * q]     = wpair.x;
            wp[2 * q + 1] = wpair.y;
        }
        const unsigned long long* vr = Vsh2 + k2 * 128 + tn * 4;
        unsigned long long vp[8];
#pragma unroll
        for (int m = 0; m < 2; m++) {
            ulonglong2 v01 = *(const ulonglong2*)(vr + m * 64);
            ulonglong2 v23 = *(const ulonglong2*)(vr + m * 64 + 2);
            vp[4 * m]     = v01.x;
            vp[4 * m + 1] = v01.y;
            vp[4 * m + 2] = v23.x;
            vp[4 * m + 3] = v23.y;
        }
#pragma unroll
        for (int j = 0; j < 8; j++)
#pragma unroll
            for (int p = 0; p < 8; p++)
                acc[j][p] = ffma2(wp[j], vp[p], acc[j][p]);
    }

    // Epilogue: lo+hi fold, add bn2 bias, store coalesced float4.
#pragma unroll
    for (int j = 0; j < 8; j++) {
        int o = o0 + j;
        float bias2 = bsh[o];
        float* orow = out + ((size_t)(b * NO + o)) * HW + n0;
#pragma unroll
        for (int m = 0; m < 2; m++) {
            float4 r;
            r.x = f2sum(acc[j][4 * m])     + bias2;
            r.y = f2sum(acc[j][4 * m + 1]) + bias2;
            r.z = f2sum(acc[j][4 * m + 2]) + bias2;
            r.w = f2sum(acc[j][4 * m + 3]) + bias2;
            *(float4*)(orow + tn * 4 + m * 64) = r;
        }
    }
}

extern "C" void kernel_launch(void* const* d_in, const int* in_sizes, int n_in,
                              void* d_out, int out_size) {
    const float* x          = (const float*)d_in[0];
    const float* attnconv_w = (const float*)d_in[1];
    const float* bn1_gamma  = (const float*)d_in[2];
    const float* bn1_beta   = (const float*)d_in[3];
    const float* bn1_mean   = (const float*)d_in[4];
    const float* bn1_var    = (const float*)d_in[5];
    const float* conv_w     = (const float*)d_in[6];
    const float* bn2_gamma  = (const float*)d_in[7];
    const float* bn2_beta   = (const float*)d_in[8];
    const float* bn2_mean   = (const float*)d_in[9];
    const float* bn2_var    = (const float*)d_in[10];
    float* out = (float*)d_out;

    attn_kernel<<<NB * NG, 256>>>(x, attnconv_w, bn1_gamma, bn1_beta,
                                  bn1_mean, bn1_var);

    // 64KB W + 32KB V + 2KB bias/scale
    size_t smem_bytes = (32 * 256 + 32 * 128) * sizeof(unsigned long long)
                      + 512 * sizeof(float);   // 100352
    cudaFuncSetAttribute(fused_gemm_kernel,
                         cudaFuncAttributeMaxDynamicSharedMemorySize,
                         (int)smem_bytes);
    dim3 grid(HW / 128, NB);
    fused_gemm_kernel<<<grid, 512, smem_bytes>>>(x, conv_w, bn2_gamma, bn2_beta,
                                                 bn2_mean, bn2_var, out);
}

// round 11
// speedup vs baseline: 4.5806x; 4.5806x over previous
#include <cuda_runtime.h>
#include <cuda_bf16.h>
#include <cstdint>

#define NB 8
#define NG 64
#define HH 256
#define HW 65536
#define NO 256
#define EPSBN 1e-5f

// per-(b,g): {coef0, coef1, coef2, bias1} with bn1 scale folded in
__device__ float g_coef[NB * NG * 4];

// ---------------------------------------------------------------------------
// Kernel 1: per (b,g) attention weights (unchanged, proven).
// ---------------------------------------------------------------------------
__global__ __launch_bounds__(256) void attn_kernel(
    const float* __restrict__ x,
    const float* __restrict__ attnconv_w,
    const float* __restrict__ bn1_gamma,
    const float* __restrict__ bn1_beta,
    const float* __restrict__ bn1_mean,
    const float* __restrict__ bn1_var) {
    int bg = blockIdx.x;            // b*64 + g
    int g  = bg & 63;
    const float* xb = x + (size_t)bg * 3 * HW;

    float qk[9];
#pragma unroll
    for (int i = 0; i < 9; i++) qk[i] = 0.f;

    for (int w = threadIdx.x; w < 4096; w += blockDim.x) {
        int wy = w >> 6, wx = w & 63;
        float mx[3], av[3];
#pragma unroll
        for (int j = 0; j < 3; j++) {
            const float4* row = (const float4*)(xb + (size_t)j * HW) + wy * 256 + wx;
            float4 r0 = row[0];
            float4 r1 = row[64];
            float4 r2 = row[128];
            float4 r3 = row[192];
            float s = (r0.x + r0.y + r0.z + r0.w) + (r1.x + r1.y + r1.z + r1.w)
                    + (r2.x + r2.y + r2.z + r2.w) + (r3.x + r3.y + r3.z + r3.w);
            float m = fmaxf(fmaxf(fmaxf(r0.x, r0.y), fmaxf(r0.z, r0.w)),
                     fmaxf(fmaxf(fmaxf(r1.x, r1.y), fmaxf(r1.z, r1.w)),
                     fmaxf(fmaxf(fmaxf(r2.x, r2.y), fmaxf(r2.z, r2.w)),
                           fmaxf(fmaxf(r3.x, r3.y), fmaxf(r3.z, r3.w)))));
            mx[j] = m;
            av[j] = s * (1.f / 16.f);
        }
#pragma unroll
        for (int i = 0; i < 3; i++)
#pragma unroll
            for (int j = 0; j < 3; j++)
                qk[i * 3 + j] += mx[i] * av[j];
    }

    __shared__ float red[8][9];
    int lane = threadIdx.x & 31, warp = threadIdx.x >> 5;
#pragma unroll
    for (int i = 0; i < 9; i++) {
        float v = qk[i];
#pragma unroll
        for (int o = 16; o > 0; o >>= 1) v += __shfl_down_sync(0xffffffffu, v, o);
        if (lane == 0) red[warp][i] = v;
    }
    __syncthreads();

    if (threadIdx.x == 0) {
        float q9[9];
#pragma unroll
        for (int i = 0; i < 9; i++) {
            float s = 0.f;
#pragma unroll
            for (int w8 = 0; w8 < 8; w8++) s += red[w8][i];
            q9[i] = s;
        }
        float w0 = attnconv_w[g * 3 + 0];
        float w1 = attnconv_w[g * 3 + 1];
        float w2 = attnconv_w[g * 3 + 2];
        float t[3];
#pragma unroll
        for (int j = 0; j < 3; j++)
            t[j] = (q9[j] * w0 + q9[3 + j] * w1 + q9[6 + j] * w2) * (4.0f / HH);
        float m = fmaxf(t[0], fmaxf(t[1], t[2]));
        float e0 = expf(t[0] - m), e1 = expf(t[1] - m), e2 = expf(t[2] - m);
        float inv = 1.f / (e0 + e1 + e2);
        float s1 = bn1_gamma[g] * rsqrtf(bn1_var[g] + EPSBN);
        float* cp = &g_coef[bg * 4];
        cp[0] = e0 * inv * s1;
        cp[1] = e1 * inv * s1;
        cp[2] = e2 * inv * s1;
        cp[3] = bn1_beta[g] - s1 * bn1_mean[g];
    }
}

// ---------------------------------------------------------------------------
// mma.sync / ldmatrix helpers (standard PTX, no sm_103a-gated features)
// ---------------------------------------------------------------------------
__device__ __forceinline__ uint32_t smem_u32(const void* p) {
    uint32_t a;
    asm("{ .reg .u64 t; cvta.to.shared.u64 t, %1; cvt.u32.u64 %0, t; }"
        : "=r"(a) : "l"(p));
    return a;
}
__device__ __forceinline__ void ldmx4(uint32_t& r0, uint32_t& r1,
                                      uint32_t& r2, uint32_t& r3,
                                      uint32_t addr) {
    asm volatile(
        "ldmatrix.sync.aligned.m8n8.x4.shared.b16 {%0,%1,%2,%3}, [%4];"
        : "=r"(r0), "=r"(r1), "=r"(r2), "=r"(r3) : "r"(addr));
}
__device__ __forceinline__ void mma16816(float* c, uint32_t a0, uint32_t a1,
                                         uint32_t a2, uint32_t a3,
                                         uint32_t b0, uint32_t b1) {
    asm volatile(
        "mma.sync.aligned.m16n8k16.row.col.f32.bf16.bf16.f32 "
        "{%0,%1,%2,%3}, {%4,%5,%6,%7}, {%8,%9}, {%0,%1,%2,%3};"
        : "+f"(c[0]), "+f"(c[1]), "+f"(c[2]), "+f"(c[3])
        : "r"(a0), "r"(a1), "r"(a2), "r"(a3), "r"(b0), "r"(b1));
}
__device__ __forceinline__ void split_bf16(float v, __nv_bfloat16& h,
                                           __nv_bfloat16& l) {
    h = __float2bfloat16(v);
    l = __float2bfloat16(v - __bfloat162float(h));
}

// ---------------------------------------------------------------------------
// Kernel 2: HMMA GEMM.  D[256 o][128 px] = W[256,K] @ V[128,K]^T  (K-major)
// W cols: [hi(64) | lo(64)]; V cols: [hi(64) | lo(64)]; segments:
//   Whi*Vhi + Whi*Vlo + Wlo*Vhi  (lo*lo ~2^-32, dropped).
// Row stride 272B -> ldmatrix conflict-free (272/4 = 68 == 4 mod 32).
// 512 threads / 16 warps; warp w: o strip [16w,16w+16) x 128 px.
// ---------------------------------------------------------------------------
#define WSTRIDE 272
#define VSTRIDE 272
#define SM_W    0
#define SM_V    69632            // 256*272
#define SM_BIAS 104448           // 69632 + 128*272
#define SM_TOT  105472           // + 256*4

__global__ __launch_bounds__(512, 1) void gemm_mma_kernel(
    const float* __restrict__ x,
    const float* __restrict__ conv_w,
    const float* __restrict__ bn2_gamma,
    const float* __restrict__ bn2_beta,
    const float* __restrict__ bn2_mean,
    const float* __restrict__ bn2_var,
    float* __restrict__ out) {
    extern __shared__ char sm[];
    char* Wsh = sm + SM_W;
    char* Vsh = sm + SM_V;
    float* bias = (float*)(sm + SM_BIAS);

    int tid = threadIdx.x, warp = tid >> 5, lane = tid & 31;
    int b = blockIdx.y, n0 = blockIdx.x * 128;

    // ---- Stage W (bn2-folded, bf16 hi|lo), one thread per output o ----
    if (tid < 256) {
        int o = tid;
        float s2 = bn2_gamma[o] * rsqrtf(bn2_var[o] + EPSBN);
        bias[o] = bn2_beta[o] - s2 * bn2_mean[o];
        const float4* wr = (const float4*)(conv_w + o * 64);
        char* row = Wsh + o * WSTRIDE;
#pragma unroll
        for (int q = 0; q < 16; q++) {
            float4 w4 = wr[q];
            float w0 = w4.x * s2, w1 = w4.y * s2, w2 = w4.z * s2, w3 = w4.w * s2;
            __nv_bfloat16 h0, h1, h2, h3, l0, l1, l2, l3;
            split_bf16(w0, h0, l0); split_bf16(w1, h1, l1);
            split_bf16(w2, h2, l2); split_bf16(w3, h3, l3);
            int c = q * 4;
            *(__nv_bfloat162*)(row + 2 * c)             = __nv_bfloat162(h0, h1);
            *(__nv_bfloat162*)(row + 2 * (c + 2))       = __nv_bfloat162(h2, h3);
            *(__nv_bfloat162*)(row + 128 + 2 * c)       = __nv_bfloat162(l0, l1);
            *(__nv_bfloat162*)(row + 128 + 2 * (c + 2)) = __nv_bfloat162(l2, l3);
        }
    }

    // ---- Build V tile: warp handles 2 g-pairs, lanes sweep px (coalesced) ----
#pragma unroll
    for (int j = 0; j < 2; j++) {
        int g0 = (warp * 2 + j) * 2;      // even g of the pair
        const float* cp = &g_coef[(b * 64 + g0) * 4];
        float c00 = cp[0], c01 = cp[1], c02 = cp[2], c03 = cp[3];
        float c10 = cp[4], c11 = cp[5], c12 = cp[6], c13 = cp[7];
        const float* x0 = x + ((size_t)(b * 192 + g0 * 3)) * HW + n0;
#pragma unroll
        for (int i = 0; i < 4; i++) {
            int px = lane + 32 * i;
            float a0 = x0[px],          a1 = x0[px + HW],     a2 = x0[px + 2 * HW];
            float b0 = x0[px + 3 * HW], b1 = x0[px + 4 * HW], b2 = x0[px + 5 * HW];
            float v0 = fmaxf(fmaf(c00, a0, fmaf(c01, a1, fmaf(c02, a2, c03))), 0.f);
            float v1 = fmaxf(fmaf(c10, b0, fmaf(c11, b1, fmaf(c12, b2, c13))), 0.f);
            __nv_bfloat16 h0, h1, l0, l1;
            split_bf16(v0, h0, l0);
            split_bf16(v1, h1, l1);
            char* vrow = Vsh + px * VSTRIDE;
            *(__nv_bfloat162*)(vrow + 2 * g0)       = __nv_bfloat162(h0, h1);
            *(__nv_bfloat162*)(vrow + 128 + 2 * g0) = __nv_bfloat162(l0, l1);
        }
    }
    __syncthreads();

    // ---- Mainloop ----
    int o0 = warp * 16;
    // A (W) ldmatrix lane address: lanes 0-15 -> rows o0+l, byte 0;
    //                              lanes 16-31 -> rows o0+(l-16), byte 16.
    uint32_t aBase = smem_u32(Wsh) + (uint32_t)(o0 + (lane & 15)) * WSTRIDE
                   + (uint32_t)((lane >> 4) << 4);
    // B (V): r0 rows 0-7 off0, r1 rows 0-7 off16, r2 rows 8-15 off0, r3 rows 8-15 off16
    uint32_t vRow = (uint32_t)((lane & 7) + ((lane >> 4) << 3));
    uint32_t bBase = smem_u32(Vsh) + vRow * VSTRIDE
                   + (uint32_t)(((lane >> 3) & 1) << 4);

    float c[16][4];
#pragma unroll
    for (int t = 0; t < 16; t++)
#pragma unroll
        for (int q = 0; q < 4; q++) c[t][q] = 0.f;

    const int segW[3] = {0, 0, 128};
    const int segV[3] = {0, 128, 0};
#pragma unroll
    for (int s = 0; s < 3; s++) {
#pragma unroll
        for (int ks = 0; ks < 4; ks++) {
            uint32_t a0, a1, a2, a3;
            ldmx4(a0, a1, a2, a3, aBase + segW[s] + ks * 32);
#pragma unroll
            for (int p = 0; p < 8; p++) {
                uint32_t b0, b1, b2, b3;
                ldmx4(b0, b1, b2, b3,
                      bBase + segV[s] + ks * 32 + p * (16 * VSTRIDE));
                mma16816(c[2 * p],     a0, a1, a2, a3, b0, b1);
                mma16816(c[2 * p + 1], a0, a1, a2, a3, b2, b3);
            }
        }
    }

    // ---- Epilogue: px pairs -> float2; each STG.64 fills 8 full 32B sectors ----
    int px0 = 2 * (lane & 3);
    int olo = o0 + (lane >> 2), ohi = olo + 8;
    float blo = bias[olo], bhi = bias[ohi];
    float* outb = out + ((size_t)b * NO) * HW + n0;
    float* rlo = outb + (size_t)olo * HW;
    float* rhi = outb + (size_t)ohi * HW;
#pragma unroll
    for (int t = 0; t < 16; t++) {
        int px = t * 8 + px0;
        *(float2*)(rlo + px) = make_float2(c[t][0] + blo, c[t][1] + blo);
        *(float2*)(rhi + px) = make_float2(c[t][2] + bhi, c[t][3] + bhi);
    }
}

extern "C" void kernel_launch(void* const* d_in, const int* in_sizes, int n_in,
                              void* d_out, int out_size) {
    const float* x          = (const float*)d_in[0];
    const float* attnconv_w = (const float*)d_in[1];
    const float* bn1_gamma  = (const float*)d_in[2];
    const float* bn1_beta   = (const float*)d_in[3];
    const float* bn1_mean   = (const float*)d_in[4];
    const float* bn1_var    = (const float*)d_in[5];
    const float* conv_w     = (const float*)d_in[6];
    const float* bn2_gamma  = (const float*)d_in[7];
    const float* bn2_beta   = (const float*)d_in[8];
    const float* bn2_mean   = (const float*)d_in[9];
    const float* bn2_var    = (const float*)d_in[10];
    float* out = (float*)d_out;

    attn_kernel<<<NB * NG, 256>>>(x, attnconv_w, bn1_gamma, bn1_beta,
                                  bn1_mean, bn1_var);

    cudaFuncSetAttribute(gemm_mma_kernel,
                         cudaFuncAttributeMaxDynamicSharedMemorySize,
                         SM_TOT);
    dim3 grid(HW / 128, NB);
    gemm_mma_kernel<<<grid, 512, SM_TOT>>>(x, conv_w, bn2_gamma, bn2_beta,
                                           bn2_mean, bn2_var, out);
}

// round 13
// speedup vs baseline: 5.8903x; 1.2859x over previous
#include <cuda_runtime.h>
#include <cuda_bf16.h>
#include <cstdint>

#define NB 8
#define NG 64
#define HH 256
#define HW 65536
#define NO 256
#define EPSBN 1e-5f

// per-(b,g): {coef0, coef1, coef2, bias1} with bn1 scale folded in
__device__ float g_coef[NB * NG * 4];

// ---------------------------------------------------------------------------
// Kernel 1: per (b,g) attention weights (unchanged, proven).
// ---------------------------------------------------------------------------
__global__ __launch_bounds__(256) void attn_kernel(
    const float* __restrict__ x,
    const float* __restrict__ attnconv_w,
    const float* __restrict__ bn1_gamma,
    const float* __restrict__ bn1_beta,
    const float* __restrict__ bn1_mean,
    const float* __restrict__ bn1_var) {
    int bg = blockIdx.x;            // b*64 + g
    int g  = bg & 63;
    const float* xb = x + (size_t)bg * 3 * HW;

    float qk[9];
#pragma unroll
    for (int i = 0; i < 9; i++) qk[i] = 0.f;

    for (int w = threadIdx.x; w < 4096; w += blockDim.x) {
        int wy = w >> 6, wx = w & 63;
        float mx[3], av[3];
#pragma unroll
        for (int j = 0; j < 3; j++) {
            const float4* row = (const float4*)(xb + (size_t)j * HW) + wy * 256 + wx;
            float4 r0 = row[0];
            float4 r1 = row[64];
            float4 r2 = row[128];
            float4 r3 = row[192];
            float s = (r0.x + r0.y + r0.z + r0.w) + (r1.x + r1.y + r1.z + r1.w)
                    + (r2.x + r2.y + r2.z + r2.w) + (r3.x + r3.y + r3.z + r3.w);
            float m = fmaxf(fmaxf(fmaxf(r0.x, r0.y), fmaxf(r0.z, r0.w)),
                     fmaxf(fmaxf(fmaxf(r1.x, r1.y), fmaxf(r1.z, r1.w)),
                     fmaxf(fmaxf(fmaxf(r2.x, r2.y), fmaxf(r2.z, r2.w)),
                           fmaxf(fmaxf(r3.x, r3.y), fmaxf(r3.z, r3.w)))));
            mx[j] = m;
            av[j] = s * (1.f / 16.f);
        }
#pragma unroll
        for (int i = 0; i < 3; i++)
#pragma unroll
            for (int j = 0; j < 3; j++)
                qk[i * 3 + j] += mx[i] * av[j];
    }

    __shared__ float red[8][9];
    int lane = threadIdx.x & 31, warp = threadIdx.x >> 5;
#pragma unroll
    for (int i = 0; i < 9; i++) {
        float v = qk[i];
#pragma unroll
        for (int o = 16; o > 0; o >>= 1) v += __shfl_down_sync(0xffffffffu, v, o);
        if (lane == 0) red[warp][i] = v;
    }
    __syncthreads();

    if (threadIdx.x == 0) {
        float q9[9];
#pragma unroll
        for (int i = 0; i < 9; i++) {
            float s = 0.f;
#pragma unroll
            for (int w8 = 0; w8 < 8; w8++) s += red[w8][i];
            q9[i] = s;
        }
        float w0 = attnconv_w[g * 3 + 0];
        float w1 = attnconv_w[g * 3 + 1];
        float w2 = attnconv_w[g * 3 + 2];
        float t[3];
#pragma unroll
        for (int j = 0; j < 3; j++)
            t[j] = (q9[j] * w0 + q9[3 + j] * w1 + q9[6 + j] * w2) * (4.0f / HH);
        float m = fmaxf(t[0], fmaxf(t[1], t[2]));
        float e0 = expf(t[0] - m), e1 = expf(t[1] - m), e2 = expf(t[2] - m);
        float inv = 1.f / (e0 + e1 + e2);
        float s1 = bn1_gamma[g] * rsqrtf(bn1_var[g] + EPSBN);
        float* cp = &g_coef[bg * 4];
        cp[0] = e0 * inv * s1;
        cp[1] = e1 * inv * s1;
        cp[2] = e2 * inv * s1;
        cp[3] = bn1_beta[g] - s1 * bn1_mean[g];
    }
}

// ---------------------------------------------------------------------------
// mma.sync / ldmatrix helpers (standard PTX, no sm_103a-gated features)
// ---------------------------------------------------------------------------
__device__ __forceinline__ uint32_t smem_u32(const void* p) {
    uint32_t a;
    asm("{ .reg .u64 t; cvta.to.shared.u64 t, %1; cvt.u32.u64 %0, t; }"
        : "=r"(a) : "l"(p));
    return a;
}
__device__ __forceinline__ void ldmx4(uint32_t& r0, uint32_t& r1,
                                      uint32_t& r2, uint32_t& r3,
                                      uint32_t addr) {
    asm volatile(
        "ldmatrix.sync.aligned.m8n8.x4.shared.b16 {%0,%1,%2,%3}, [%4];"
        : "=r"(r0), "=r"(r1), "=r"(r2), "=r"(r3) : "r"(addr));
}
__device__ __forceinline__ void mma16816(float* c, uint32_t a0, uint32_t a1,
                                         uint32_t a2, uint32_t a3,
                                         uint32_t b0, uint32_t b1) {
    asm volatile(
        "mma.sync.aligned.m16n8k16.row.col.f32.bf16.bf16.f32 "
        "{%0,%1,%2,%3}, {%4,%5,%6,%7}, {%8,%9}, {%0,%1,%2,%3};"
        : "+f"(c[0]), "+f"(c[1]), "+f"(c[2]), "+f"(c[3])
        : "r"(a0), "r"(a1), "r"(a2), "r"(a3), "r"(b0), "r"(b1));
}
__device__ __forceinline__ void split_bf16(float v, __nv_bfloat16& h,
                                           __nv_bfloat16& l) {
    h = __float2bfloat16(v);
    l = __float2bfloat16(v - __bfloat162float(h));
}

// ---------------------------------------------------------------------------
// Kernel 2: HMMA GEMM.  D[256 o][128 px] = W[256,K] @ V[128,K]^T  (K-major)
// W cols: [hi(64) | lo(64)]; V cols: [hi(64) | lo(64)]; segments:
//   Whi*Vhi + Whi*Vlo + Wlo*Vhi  (lo*lo ~2^-32, dropped).
// Row stride 272B -> ldmatrix conflict-free (272 == 16 mod 128).
// 512 threads / 16 warps; warp tile 32 o x 64 px (8 o-strips x 2 px-halves):
// per k16-step 2 A-ldmatrix + 4 B-ldmatrix + 16 MMA (was 1+8+16 at 16x128).
// ---------------------------------------------------------------------------
#define WSTRIDE 272
#define VSTRIDE 272
#define SM_W    0
#define SM_V    69632            // 256*272
#define SM_BIAS 104448           // 69632 + 128*272
#define SM_TOT  105472           // + 256*4

__global__ __launch_bounds__(512, 1) void gemm_mma_kernel(
    const float* __restrict__ x,
    const float* __restrict__ conv_w,
    const float* __restrict__ bn2_gamma,
    const float* __restrict__ bn2_beta,
    const float* __restrict__ bn2_mean,
    const float* __restrict__ bn2_var,
    float* __restrict__ out) {
    extern __shared__ char sm[];
    char* Wsh = sm + SM_W;
    char* Vsh = sm + SM_V;
    float* bias = (float*)(sm + SM_BIAS);

    int tid = threadIdx.x, warp = tid >> 5, lane = tid & 31;
    int b = blockIdx.y, n0 = blockIdx.x * 128;

    // ---- Stage W (bn2-folded, bf16 hi|lo), one thread per output o ----
    if (tid < 256) {
        int o = tid;
        float s2 = bn2_gamma[o] * rsqrtf(bn2_var[o] + EPSBN);
        bias[o] = bn2_beta[o] - s2 * bn2_mean[o];
        const float4* wr = (const float4*)(conv_w + o * 64);
        char* row = Wsh + o * WSTRIDE;
#pragma unroll
        for (int q = 0; q < 16; q++) {
            float4 w4 = wr[q];
            float w0 = w4.x * s2, w1 = w4.y * s2, w2 = w4.z * s2, w3 = w4.w * s2;
            __nv_bfloat16 h0, h1, h2, h3, l0, l1, l2, l3;
            split_bf16(w0, h0, l0); split_bf16(w1, h1, l1);
            split_bf16(w2, h2, l2); split_bf16(w3, h3, l3);
            int c = q * 4;
            *(__nv_bfloat162*)(row + 2 * c)             = __nv_bfloat162(h0, h1);
            *(__nv_bfloat162*)(row + 2 * (c + 2))       = __nv_bfloat162(h2, h3);
            *(__nv_bfloat162*)(row + 128 + 2 * c)       = __nv_bfloat162(l0, l1);
            *(__nv_bfloat162*)(row + 128 + 2 * (c + 2)) = __nv_bfloat162(l2, l3);
        }
    }

    // ---- Build V tile: warp handles 2 g-pairs, lanes sweep px (coalesced) ----
#pragma unroll
    for (int j = 0; j < 2; j++) {
        int g0 = (warp * 2 + j) * 2;      // even g of the pair
        const float* cp = &g_coef[(b * 64 + g0) * 4];
        float c00 = cp[0], c01 = cp[1], c02 = cp[2], c03 = cp[3];
        float c10 = cp[4], c11 = cp[5], c12 = cp[6], c13 = cp[7];
        const float* x0 = x + ((size_t)(b * 192 + g0 * 3)) * HW + n0;
#pragma unroll
        for (int i = 0; i < 4; i++) {
            int px = lane + 32 * i;
            float a0 = x0[px],          a1 = x0[px + HW],     a2 = x0[px + 2 * HW];
            float b0 = x0[px + 3 * HW], b1 = x0[px + 4 * HW], b2 = x0[px + 5 * HW];
            float v0 = fmaxf(fmaf(c00, a0, fmaf(c01, a1, fmaf(c02, a2, c03))), 0.f);
            float v1 = fmaxf(fmaf(c10, b0, fmaf(c11, b1, fmaf(c12, b2, c13))), 0.f);
            __nv_bfloat16 h0, h1, l0, l1;
            split_bf16(v0, h0, l0);
            split_bf16(v1, h1, l1);
            char* vrow = Vsh + px * VSTRIDE;
            *(__nv_bfloat162*)(vrow + 2 * g0)       = __nv_bfloat162(h0, h1);
            *(__nv_bfloat162*)(vrow + 128 + 2 * g0) = __nv_bfloat162(l0, l1);
        }
    }
    __syncthreads();

    // ---- Mainloop: warp tile 32 o x 64 px ----
    int o0  = (warp & 7) * 32;    // o strip
    int pxh = warp >> 3;          // px half (0/1), 64 px each
    // A (W) ldmatrix lane address: lanes 0-15 -> rows o0+l, byte 0;
    //                              lanes 16-31 -> rows o0+(l-16), byte 16.
    uint32_t aBase = smem_u32(Wsh) + (uint32_t)(o0 + (lane & 15)) * WSTRIDE
                   + (uint32_t)((lane >> 4) << 4);
    // B (V): m0 rows0-7 off0, m1 rows0-7 off16, m2 rows8-15 off0, m3 rows8-15 off16
    uint32_t vRow = (uint32_t)((lane & 7) + ((lane >> 4) << 3));
    uint32_t bBase = smem_u32(Vsh) + (uint32_t)(pxh * 64 + vRow) * VSTRIDE
                   + (uint32_t)(((lane >> 3) & 1) << 4);

    float c[2][8][4];
#pragma unroll
    for (int u = 0; u < 2; u++)
#pragma unroll
        for (int t = 0; t < 8; t++)
#pragma unroll
            for (int q = 0; q < 4; q++) c[u][t][q] = 0.f;

    const int segW[3] = {0, 0, 128};
    const int segV[3] = {0, 128, 0};
#pragma unroll
    for (int s = 0; s < 3; s++) {
#pragma unroll
        for (int ks = 0; ks < 4; ks++) {
            uint32_t a[2][4];
            ldmx4(a[0][0], a[0][1], a[0][2], a[0][3],
                  aBase + segW[s] + ks * 32);
            ldmx4(a[1][0], a[1][1], a[1][2], a[1][3],
                  aBase + 16 * WSTRIDE + segW[s] + ks * 32);
#pragma unroll
            for (int p = 0; p < 4; p++) {
                uint32_t b0, b1, b2, b3;
                ldmx4(b0, b1, b2, b3,
                      bBase + segV[s] + ks * 32 + p * (16 * VSTRIDE));
#pragma unroll
                for (int u = 0; u < 2; u++) {
                    mma16816(c[u][2 * p],     a[u][0], a[u][1], a[u][2], a[u][3], b0, b1);
                    mma16816(c[u][2 * p + 1], a[u][0], a[u][1], a[u][2], a[u][3], b2, b3);
                }
            }
        }
    }

    // ---- Epilogue: px pairs -> float2; each STG.64 run fills full sectors ----
    int px0 = 2 * (lane & 3);
    float* outb = out + ((size_t)b * NO) * HW + n0 + pxh * 64;
#pragma unroll
    for (int u = 0; u < 2; u++) {
        int olo = o0 + u * 16 + (lane >> 2), ohi = olo + 8;
        float blo = bias[olo], bhi = bias[ohi];
        float* rlo = outb + (size_t)olo * HW;
        float* rhi = outb + (size_t)ohi * HW;
#pragma unroll
        for (int t = 0; t < 8; t++) {
            int px = t * 8 + px0;
            *(float2*)(rlo + px) = make_float2(c[u][t][0] + blo, c[u][t][1] + blo);
            *(float2*)(rhi + px) = make_float2(c[u][t][2] + bhi, c[u][t][3] + bhi);
        }
    }
}

extern "C" void kernel_launch(void* const* d_in, const int* in_sizes, int n_in,
                              void* d_out, int out_size) {
    const float* x          = (const float*)d_in[0];
    const float* attnconv_w = (const float*)d_in[1];
    const float* bn1_gamma  = (const float*)d_in[2];
    const float* bn1_beta   = (const float*)d_in[3];
    const float* bn1_mean   = (const float*)d_in[4];
    const float* bn1_var    = (const float*)d_in[5];
    const float* conv_w     = (const float*)d_in[6];
    const float* bn2_gamma  = (const float*)d_in[7];
    const float* bn2_beta   = (const float*)d_in[8];
    const float* bn2_mean   = (const float*)d_in[9];
    const float* bn2_var    = (const float*)d_in[10];
    float* out = (float*)d_out;

    attn_kernel<<<NB * NG, 256>>>(x, attnconv_w, bn1_gamma, bn1_beta,
                                  bn1_mean, bn1_var);

    cudaFuncSetAttribute(gemm_mma_kernel,
                         cudaFuncAttributeMaxDynamicSharedMemorySize,
                         SM_TOT);
    dim3 grid(HW / 128, NB);
    gemm_mma_kernel<<<grid, 512, SM_TOT>>>(x, conv_w, bn2_gamma, bn2_beta,
                                           bn2_mean, bn2_var, out);
}

// round 14
// speedup vs baseline: 6.5961x; 1.1198x over previous
#include <cuda_runtime.h>
#include <cuda_bf16.h>
#include <cstdint>

#define NB 8
#define NG 64
#define HH 256
#define HW 65536
#define NO 256
#define EPSBN 1e-5f
#define TILES 4

// per-(b,g): {coef0, coef1, coef2, bias1} with bn1 scale folded in
__device__ float g_coef[NB * NG * 4];

// ---------------------------------------------------------------------------
// Kernel 1: per (b,g) attention weights (unchanged, proven).
// ---------------------------------------------------------------------------
__global__ __launch_bounds__(256) void attn_kernel(
    const float* __restrict__ x,
    const float* __restrict__ attnconv_w,
    const float* __restrict__ bn1_gamma,
    const float* __restrict__ bn1_beta,
    const float* __restrict__ bn1_mean,
    const float* __restrict__ bn1_var) {
    int bg = blockIdx.x;            // b*64 + g
    int g  = bg & 63;
    const float* xb = x + (size_t)bg * 3 * HW;

    float qk[9];
#pragma unroll
    for (int i = 0; i < 9; i++) qk[i] = 0.f;

    for (int w = threadIdx.x; w < 4096; w += blockDim.x) {
        int wy = w >> 6, wx = w & 63;
        float mx[3], av[3];
#pragma unroll
        for (int j = 0; j < 3; j++) {
            const float4* row = (const float4*)(xb + (size_t)j * HW) + wy * 256 + wx;
            float4 r0 = row[0];
            float4 r1 = row[64];
            float4 r2 = row[128];
            float4 r3 = row[192];
            float s = (r0.x + r0.y + r0.z + r0.w) + (r1.x + r1.y + r1.z + r1.w)
                    + (r2.x + r2.y + r2.z + r2.w) + (r3.x + r3.y + r3.z + r3.w);
            float m = fmaxf(fmaxf(fmaxf(r0.x, r0.y), fmaxf(r0.z, r0.w)),
                     fmaxf(fmaxf(fmaxf(r1.x, r1.y), fmaxf(r1.z, r1.w)),
                     fmaxf(fmaxf(fmaxf(r2.x, r2.y), fmaxf(r2.z, r2.w)),
                           fmaxf(fmaxf(r3.x, r3.y), fmaxf(r3.z, r3.w)))));
            mx[j] = m;
            av[j] = s * (1.f / 16.f);
        }
#pragma unroll
        for (int i = 0; i < 3; i++)
#pragma unroll
            for (int j = 0; j < 3; j++)
                qk[i * 3 + j] += mx[i] * av[j];
    }

    __shared__ float red[8][9];
    int lane = threadIdx.x & 31, warp = threadIdx.x >> 5;
#pragma unroll
    for (int i = 0; i < 9; i++) {
        float v = qk[i];
#pragma unroll
        for (int o = 16; o > 0; o >>= 1) v += __shfl_down_sync(0xffffffffu, v, o);
        if (lane == 0) red[warp][i] = v;
    }
    __syncthreads();

    if (threadIdx.x == 0) {
        float q9[9];
#pragma unroll
        for (int i = 0; i < 9; i++) {
            float s = 0.f;
#pragma unroll
            for (int w8 = 0; w8 < 8; w8++) s += red[w8][i];
            q9[i] = s;
        }
        float w0 = attnconv_w[g * 3 + 0];
        float w1 = attnconv_w[g * 3 + 1];
        float w2 = attnconv_w[g * 3 + 2];
        float t[3];
#pragma unroll
        for (int j = 0; j < 3; j++)
            t[j] = (q9[j] * w0 + q9[3 + j] * w1 + q9[6 + j] * w2) * (4.0f / HH);
        float m = fmaxf(t[0], fmaxf(t[1], t[2]));
        float e0 = expf(t[0] - m), e1 = expf(t[1] - m), e2 = expf(t[2] - m);
        float inv = 1.f / (e0 + e1 + e2);
        float s1 = bn1_gamma[g] * rsqrtf(bn1_var[g] + EPSBN);
        float* cp = &g_coef[bg * 4];
        cp[0] = e0 * inv * s1;
        cp[1] = e1 * inv * s1;
        cp[2] = e2 * inv * s1;
        cp[3] = bn1_beta[g] - s1 * bn1_mean[g];
    }
}

// ---------------------------------------------------------------------------
// mma.sync / ldmatrix / cp.async helpers (standard PTX)
// ---------------------------------------------------------------------------
__device__ __forceinline__ uint32_t smem_u32(const void* p) {
    uint32_t a;
    asm("{ .reg .u64 t; cvta.to.shared.u64 t, %1; cvt.u32.u64 %0, t; }"
        : "=r"(a) : "l"(p));
    return a;
}
__device__ __forceinline__ void ldmx4(uint32_t& r0, uint32_t& r1,
                                      uint32_t& r2, uint32_t& r3,
                                      uint32_t addr) {
    asm volatile(
        "ldmatrix.sync.aligned.m8n8.x4.shared.b16 {%0,%1,%2,%3}, [%4];"
        : "=r"(r0), "=r"(r1), "=r"(r2), "=r"(r3) : "r"(addr));
}
__device__ __forceinline__ void mma16816(float* c, uint32_t a0, uint32_t a1,
                                         uint32_t a2, uint32_t a3,
                                         uint32_t b0, uint32_t b1) {
    asm volatile(
        "mma.sync.aligned.m16n8k16.row.col.f32.bf16.bf16.f32 "
        "{%0,%1,%2,%3}, {%4,%5,%6,%7}, {%8,%9}, {%0,%1,%2,%3};"
        : "+f"(c[0]), "+f"(c[1]), "+f"(c[2]), "+f"(c[3])
        : "r"(a0), "r"(a1), "r"(a2), "r"(a3), "r"(b0), "r"(b1));
}
__device__ __forceinline__ void split_bf16(float v, __nv_bfloat16& h,
                                           __nv_bfloat16& l) {
    h = __float2bfloat16(v);
    l = __float2bfloat16(v - __bfloat162float(h));
}

// ---------------------------------------------------------------------------
// Kernel 2: persistent 4-tile HMMA GEMM with cp.async-pipelined V staging.
//   D[256 o][128 px] = W[256,K] @ V[128,K]^T, K=192 (3-seg bf16 split).
// Per tile: raw x (192ch x 128px f32, 98KB) prefetched via cp.async while the
// PREVIOUS tile's MMA runs; convert reads smem raw -> bf16 hi|lo V tile.
// W/bias/coefs staged once per CTA.  Mainloop/epilogue identical to R12.
// ---------------------------------------------------------------------------
#define WSTRIDE 272
#define VSTRIDE 272
#define SM_W    0                // 256*272      = 69632
#define SM_V    69632            // 128*272      = 34816
#define SM_RAW  104448           // 192*512      = 98304
#define SM_BIAS 202752           // 256 f32
#define SM_COEF 203776           // 256 f32
#define SM_TOT  204800

__device__ __forceinline__ void prefetch_raw(const float* __restrict__ x,
                                             int b, int n0, uint32_t rawb) {
    int tid = threadIdx.x;
#pragma unroll
    for (int q = 0; q < 12; q++) {
        int c = tid + q * 512;           // chunk id: 192 rows x 32 chunks
        int ch = c >> 5;
        int off = (c & 31) << 4;         // byte offset within 512B row
        const char* src = (const char*)(x + ((size_t)(b * 192 + ch)) * HW + n0) + off;
        uint32_t dst = rawb + (uint32_t)(ch * 512 + off);
        asm volatile("cp.async.cg.shared.global [%0], [%1], 16;"
                     :: "r"(dst), "l"(src));
    }
    asm volatile("cp.async.commit_group;" ::: "memory");
}

__global__ __launch_bounds__(512, 1) void gemm_mma_kernel(
    const float* __restrict__ x,
    const float* __restrict__ conv_w,
    const float* __restrict__ bn2_gamma,
    const float* __restrict__ bn2_beta,
    const float* __restrict__ bn2_mean,
    const float* __restrict__ bn2_var,
    float* __restrict__ out) {
    extern __shared__ char sm[];
    char* Wsh = sm + SM_W;
    char* Vsh = sm + SM_V;
    float* raw = (float*)(sm + SM_RAW);
    float* bias = (float*)(sm + SM_BIAS);
    float* csh  = (float*)(sm + SM_COEF);

    int tid = threadIdx.x, warp = tid >> 5, lane = tid & 31;
    int b = blockIdx.y;
    int n0_base = blockIdx.x * (TILES * 128);
    uint32_t rawb = smem_u32(raw);

    // Prefetch tile 0 FIRST so its DRAM latency hides under W staging.
    prefetch_raw(x, b, n0_base, rawb);

    // ---- Stage W (bn2-folded, bf16 hi|lo) + bias (tid<256) / coefs (tid>=256) ----
    if (tid < 256) {
        int o = tid;
        float s2 = bn2_gamma[o] * rsqrtf(bn2_var[o] + EPSBN);
        bias[o] = bn2_beta[o] - s2 * bn2_mean[o];
        const float4* wr = (const float4*)(conv_w + o * 64);
        char* row = Wsh + o * WSTRIDE;
#pragma unroll
        for (int q = 0; q < 16; q++) {
            float4 w4 = wr[q];
            float w0 = w4.x * s2, w1 = w4.y * s2, w2 = w4.z * s2, w3 = w4.w * s2;
            __nv_bfloat16 h0, h1, h2, h3, l0, l1, l2, l3;
            split_bf16(w0, h0, l0); split_bf16(w1, h1, l1);
            split_bf16(w2, h2, l2); split_bf16(w3, h3, l3);
            int c = q * 4;
            *(__nv_bfloat162*)(row + 2 * c)             = __nv_bfloat162(h0, h1);
            *(__nv_bfloat162*)(row + 2 * (c + 2))       = __nv_bfloat162(h2, h3);
            *(__nv_bfloat162*)(row + 128 + 2 * c)       = __nv_bfloat162(l0, l1);
            *(__nv_bfloat162*)(row + 128 + 2 * (c + 2)) = __nv_bfloat162(l2, l3);
        }
    } else {
        csh[tid - 256] = g_coef[b * 256 + (tid - 256)];
    }

    // ---- ldmatrix lane addressing (constant across tiles) ----
    int o0  = (warp & 7) * 32;    // o strip
    int pxh = warp >> 3;          // px half (0/1)
    uint32_t aBase = smem_u32(Wsh) + (uint32_t)(o0 + (lane & 15)) * WSTRIDE
                   + (uint32_t)((lane >> 4) << 4);
    uint32_t vRow = (uint32_t)((lane & 7) + ((lane >> 4) << 3));
    uint32_t bBase = smem_u32(Vsh) + (uint32_t)(pxh * 64 + vRow) * VSTRIDE
                   + (uint32_t)(((lane >> 3) & 1) << 4);

    const int segW[3] = {0, 0, 128};
    const int segV[3] = {0, 128, 0};

    for (int t = 0; t < TILES; t++) {
        int n0 = n0_base + t * 128;

        // Wait for raw(t); barrier also fences prior tile's ldmatrix reads of V.
        asm volatile("cp.async.wait_group 0;" ::: "memory");
        __syncthreads();

        // ---- Convert: raw smem -> bf16 hi|lo V tile ----
#pragma unroll
        for (int j = 0; j < 2; j++) {
            int g0 = (warp * 2 + j) * 2;          // even g of the pair
            const float* cp = csh + g0 * 4;
            float c00 = cp[0], c01 = cp[1], c02 = cp[2], c03 = cp[3];
            float c10 = cp[4], c11 = cp[5], c12 = cp[6], c13 = cp[7];
            const float* r0 = raw + (g0 * 3) * 128;
#pragma unroll
            for (int i = 0; i < 4; i++) {
                int px = lane + 32 * i;
                float a0 = r0[px],           a1 = r0[px + 128],     a2 = r0[px + 256];
                float b0 = r0[px + 384],     b1 = r0[px + 512],     b2 = r0[px + 640];
                float v0 = fmaxf(fmaf(c00, a0, fmaf(c01, a1, fmaf(c02, a2, c03))), 0.f);
                float v1 = fmaxf(fmaf(c10, b0, fmaf(c11, b1, fmaf(c12, b2, c13))), 0.f);
                __nv_bfloat16 h0, h1, l0, l1;
                split_bf16(v0, h0, l0);
                split_bf16(v1, h1, l1);
                char* vrow = Vsh + px * VSTRIDE;
                *(__nv_bfloat162*)(vrow + 2 * g0)       = __nv_bfloat162(h0, h1);
                *(__nv_bfloat162*)(vrow + 128 + 2 * g0) = __nv_bfloat162(l0, l1);
            }
        }
        __syncthreads();   // V ready; raw fully consumed

        // Prefetch next tile — lands while MMA below runs.
        if (t + 1 < TILES) prefetch_raw(x, b, n0 + 128, rawb);

        // ---- Mainloop: warp tile 32 o x 64 px ----
        float c[2][8][4];
#pragma unroll
        for (int u = 0; u < 2; u++)
#pragma unroll
            for (int tt = 0; tt < 8; tt++)
#pragma unroll
                for (int q = 0; q < 4; q++) c[u][tt][q] = 0.f;

#pragma unroll
        for (int s = 0; s < 3; s++) {
#pragma unroll
            for (int ks = 0; ks < 4; ks++) {
                uint32_t a[2][4];
                ldmx4(a[0][0], a[0][1], a[0][2], a[0][3],
                      aBase + segW[s] + ks * 32);
                ldmx4(a[1][0], a[1][1], a[1][2], a[1][3],
                      aBase + 16 * WSTRIDE + segW[s] + ks * 32);
#pragma unroll
                for (int p = 0; p < 4; p++) {
                    uint32_t b0, b1, b2, b3;
                    ldmx4(b0, b1, b2, b3,
                          bBase + segV[s] + ks * 32 + p * (16 * VSTRIDE));
#pragma unroll
                    for (int u = 0; u < 2; u++) {
                        mma16816(c[u][2 * p],     a[u][0], a[u][1], a[u][2], a[u][3], b0, b1);
                        mma16816(c[u][2 * p + 1], a[u][0], a[u][1], a[u][2], a[u][3], b2, b3);
                    }
                }
            }
        }

        // ---- Epilogue ----
        int px0 = 2 * (lane & 3);
        float* outb = out + ((size_t)b * NO) * HW + n0 + pxh * 64;
#pragma unroll
        for (int u = 0; u < 2; u++) {
            int olo = o0 + u * 16 + (lane >> 2), ohi = olo + 8;
            float blo = bias[olo], bhi = bias[ohi];
            float* rlo = outb + (size_t)olo * HW;
            float* rhi = outb + (size_t)ohi * HW;
#pragma unroll
            for (int tt = 0; tt < 8; tt++) {
                int px = tt * 8 + px0;
                *(float2*)(rlo + px) = make_float2(c[u][tt][0] + blo, c[u][tt][1] + blo);
                *(float2*)(rhi + px) = make_float2(c[u][tt][2] + bhi, c[u][tt][3] + bhi);
            }
        }
    }
}

extern "C" void kernel_launch(void* const* d_in, const int* in_sizes, int n_in,
                              void* d_out, int out_size) {
    const float* x          = (const float*)d_in[0];
    const float* attnconv_w = (const float*)d_in[1];
    const float* bn1_gamma  = (const float*)d_in[2];
    const float* bn1_beta   = (const float*)d_in[3];
    const float* bn1_mean   = (const float*)d_in[4];
    const float* bn1_var    = (const float*)d_in[5];
    const float* conv_w     = (const float*)d_in[6];
    const float* bn2_gamma  = (const float*)d_in[7];
    const float* bn2_beta   = (const float*)d_in[8];
    const float* bn2_mean   = (const float*)d_in[9];
    const float* bn2_var    = (const float*)d_in[10];
    float* out = (float*)d_out;

    attn_kernel<<<NB * NG, 256>>>(x, attnconv_w, bn1_gamma, bn1_beta,
                                  bn1_mean, bn1_var);

    cudaFuncSetAttribute(gemm_mma_kernel,
                         cudaFuncAttributeMaxDynamicSharedMemorySize,
                         SM_TOT);
    dim3 grid(HW / (TILES * 128), NB);
    gemm_mma_kernel<<<grid, 512, SM_TOT>>>(x, conv_w, bn2_gamma, bn2_beta,
                                           bn2_mean, bn2_var, out);
}